// round 7
// baseline (speedup 1.0000x reference)
#include <cuda_runtime.h>
#include <cstdint>

#define HW    65536
#define NQ    100
#define NT    32
#define NB    8
#define NROWP 112   // 7 mtiles * 16
#define NKT   4096  // k-tiles per batch (HW/16)

// ---------------- device scratch ----------------
__device__ uint4    g_bfrag[NB * NKT * 32 * 2];  // precomputed MMA B-fragments
__device__ float    g_tsum[NB * NT];
__device__ float    g_dotPM[NB * NROWP * NT];
__device__ float    g_dotSIG[NB * NROWP * NT];
__device__ float    g_sumSP[NB * NROWP];
__device__ float    g_sumSIG[NB * NROWP];
__device__ float    g_classT[NB * NT * NQ];      // [b][t][n]

// ---------------- helpers ----------------
__device__ __forceinline__ uint32_t pack_bf16(float hi, float lo) {
    uint32_t d;
    asm("cvt.rn.bf16x2.f32 %0, %1, %2;" : "=r"(d) : "f"(hi), "f"(lo));
    return d;
}

__device__ __forceinline__ void mma_bf16(float* c, const uint32_t* a,
                                         uint32_t b0, uint32_t b1) {
    asm volatile(
        "mma.sync.aligned.m16n8k16.row.col.f32.bf16.bf16.f32 "
        "{%0,%1,%2,%3}, {%4,%5,%6,%7}, {%8,%9}, {%0,%1,%2,%3};"
        : "+f"(c[0]), "+f"(c[1]), "+f"(c[2]), "+f"(c[3])
        : "r"(a[0]), "r"(a[1]), "r"(a[2]), "r"(a[3]), "r"(b0), "r"(b1));
}

// sigmoid + softplus via MUFU.TANH (2 MUFU):
__device__ __forceinline__ void elem_math(float x, float& sig, float& sp) {
    float ax = fabsf(x);
    float th;
    asm("tanh.approx.f32 %0, %1;" : "=f"(th) : "f"(ax * 0.5f));
    float sa = fmaf(th, 0.5f, 0.5f);
    sig = (x >= 0.0f) ? sa : 1.0f - sa;
    sp  = fmaxf(x, 0.0f) - __logf(sa);
}

__device__ __forceinline__ uint32_t fkey(float f) {
    uint32_t u = __float_as_uint(f);
    return (u & 0x80000000u) ? ~u : (u | 0x80000000u);
}
__device__ __forceinline__ float fkey_inv(uint32_t k) {
    uint32_t u = (k & 0x80000000u) ? (k ^ 0x80000000u) : ~k;
    return __uint_as_float(u);
}
__device__ __forceinline__ int sel4i(int a0, int a1, int a2, int a3, int s) {
    return s == 0 ? a0 : s == 1 ? a1 : s == 2 ? a2 : a3;
}

// ---------------- kernel 1: class cost (+ accumulator zeroing) ----------------
__global__ void k_class(const float* __restrict__ logits,
                        const int* __restrict__ labels) {
    int gid = blockIdx.x * 32 + threadIdx.x;            // 25600 threads
    for (int i = gid; i < NB * NROWP * NT; i += NB * NQ * 32) {
        g_dotPM[i] = 0.f; g_dotSIG[i] = 0.f;
    }
    if (gid < NB * NROWP) { g_sumSP[gid] = 0.f; g_sumSIG[gid] = 0.f; }
    if (gid < NB * NT)    { g_tsum[gid] = 0.f; }

    int b = blockIdx.x / NQ, n = blockIdx.x % NQ;
    int lane = threadIdx.x;
    __shared__ float sh[81];
    const float* L = logits + (size_t)(b * NQ + n) * 81;

    float x0 = L[lane];
    float x1 = (lane + 32 < 81) ? L[lane + 32] : -1e30f;
    float x2 = (lane + 64 < 81) ? L[lane + 64] : -1e30f;
    float m = fmaxf(x0, fmaxf(x1, x2));
    #pragma unroll
    for (int o = 16; o; o >>= 1) m = fmaxf(m, __shfl_xor_sync(0xffffffffu, m, o));

    float e0 = __expf(x0 - m);
    float e1 = (lane + 32 < 81) ? __expf(x1 - m) : 0.f;
    float e2 = (lane + 64 < 81) ? __expf(x2 - m) : 0.f;
    float s = e0 + e1 + e2;
    #pragma unroll
    for (int o = 16; o; o >>= 1) s += __shfl_xor_sync(0xffffffffu, s, o);

    sh[lane] = e0;
    if (lane + 32 < 81) sh[lane + 32] = e1;
    if (lane + 64 < 81) sh[lane + 64] = e2;
    __syncwarp();

    float inv = 1.0f / s;
    int lbl = labels[b * NT + lane];
    g_classT[(b * NT + lane) * NQ + n] = -sh[lbl] * inv;
}

// ---------------- kernel 2: target masks -> per-target sums + B-fragments ----
// Phase 1: pack per-pixel 32-target bit words into shared (+ tsum via ballot).
// Phase 2: build the MMA B-operand fragments for the block's 32 k-tiles so
// k_main never touches bit manipulation (B-frags are mtile-invariant).
__global__ __launch_bounds__(256) void k_tmask(const float* __restrict__ tgt) {
    __shared__ uint32_t sbits[512];
    const int b = blockIdx.y;
    const int tid = threadIdx.x;
    int p0 = blockIdx.x * 512 + tid * 2;
    int h = p0 >> 8, w = p0 & 255;                    // w even
    size_t base = ((size_t)b * NT) * 262144 + (size_t)(2 * h) * 512 + 2 * w;
    uint32_t w0 = 0, w1 = 0;
    #pragma unroll
    for (int t = 0; t < 32; ++t) {
        float4 v = __ldcs((const float4*)(tgt + base + (size_t)t * 262144));
        w0 |= (uint32_t)(v.x != 0.0f) << t;
        w1 |= (uint32_t)(v.z != 0.0f) << t;
    }
    sbits[tid * 2]     = w0;
    sbits[tid * 2 + 1] = w1;

    int lane = tid & 31;
    int cnt = 0;
    #pragma unroll
    for (int t = 0; t < 32; ++t) {
        unsigned m0 = __ballot_sync(0xffffffffu, (w0 >> t) & 1u);
        unsigned m1 = __ballot_sync(0xffffffffu, (w1 >> t) & 1u);
        if (lane == t) cnt = __popc(m0) + __popc(m1);
    }
    atomicAdd(&g_tsum[b * NT + lane], (float)cnt);
    __syncthreads();

    // Phase 2: 8 warps x 4 k-tiles
    const int warp = tid >> 5;
    const int kq = (lane & 3) << 1, rq = lane >> 2;
    #pragma unroll
    for (int i = 0; i < 4; ++i) {
        int ktl = warp * 4 + i;
        uint32_t t0 = sbits[ktl * 16 + kq]     >> rq;
        uint32_t t1 = sbits[ktl * 16 + kq + 1] >> rq;
        uint32_t t2 = sbits[ktl * 16 + kq + 8] >> rq;
        uint32_t t3 = sbits[ktl * 16 + kq + 9] >> rq;
        uint4 lo, hi;
        lo.x = ((t0 & 1u) * 0x3F80u)         | ((t1 & 1u) * 0x3F800000u);
        lo.y = ((t2 & 1u) * 0x3F80u)         | ((t3 & 1u) * 0x3F800000u);
        lo.z = (((t0 >> 8) & 1u) * 0x3F80u)  | (((t1 >> 8) & 1u) * 0x3F800000u);
        lo.w = (((t2 >> 8) & 1u) * 0x3F80u)  | (((t3 >> 8) & 1u) * 0x3F800000u);
        hi.x = (((t0 >> 16) & 1u) * 0x3F80u) | (((t1 >> 16) & 1u) * 0x3F800000u);
        hi.y = (((t2 >> 16) & 1u) * 0x3F80u) | (((t3 >> 16) & 1u) * 0x3F800000u);
        hi.z = (((t0 >> 24) & 1u) * 0x3F80u) | (((t1 >> 24) & 1u) * 0x3F800000u);
        hi.w = (((t2 >> 24) & 1u) * 0x3F80u) | (((t3 >> 24) & 1u) * 0x3F800000u);
        int kt = blockIdx.x * 32 + ktl;
        uint4* dst = g_bfrag + ((size_t)(b * NKT + kt) * 32 + lane) * 2;
        dst[0] = lo;
        dst[1] = hi;
    }
}

// ---------------- kernel 3: fused elementwise + dual bf16 MMA ----------------
__global__ __launch_bounds__(256) void k_main(const float* __restrict__ pm) {
    const int b = blockIdx.z, mt = blockIdx.y;
    const int warp = threadIdx.x >> 5, lane = threadIdx.x & 31;
    const int kstart = blockIdx.x * (HW / 16) + warp * (HW / 16 / 8);
    const int rq = lane >> 2;
    const int kq = (lane & 3) << 1;
    const int r_lo = mt * 16 + rq, r_hi = r_lo + 8;
    const int rl = min(r_lo, NQ - 1), rh = min(r_hi, NQ - 1);

    const float* pmb = pm + (size_t)b * NQ * HW;
    const uint4* bf  = g_bfrag + ((size_t)(b * NKT + (kstart >> 4)) * 32 + lane) * 2;

    float cpm[4][4], csg[4][4];
    #pragma unroll
    for (int i = 0; i < 4; ++i)
        #pragma unroll
        for (int j = 0; j < 4; ++j) { cpm[i][j] = 0.f; csg[i][j] = 0.f; }

    float ssp0 = 0.f, ssp1 = 0.f, ssg0 = 0.f, ssg1 = 0.f;

    #pragma unroll 4
    for (int it = 0; it < 32; ++it) {
        int k0 = kstart + it * 16 + kq;
        float2 x00 = __ldcs((const float2*)(pmb + (size_t)rl * HW + k0));
        float2 x10 = __ldcs((const float2*)(pmb + (size_t)rh * HW + k0));
        float2 x01 = __ldcs((const float2*)(pmb + (size_t)rl * HW + k0 + 8));
        float2 x11 = __ldcs((const float2*)(pmb + (size_t)rh * HW + k0 + 8));
        uint4 blo = bf[it * 64];
        uint4 bhi = bf[it * 64 + 1];

        float s00a, s00b, s10a, s10b, s01a, s01b, s11a, s11b;
        float p00a, p00b, p10a, p10b, p01a, p01b, p11a, p11b;
        elem_math(x00.x, s00a, p00a); elem_math(x00.y, s00b, p00b);
        elem_math(x10.x, s10a, p10a); elem_math(x10.y, s10b, p10b);
        elem_math(x01.x, s01a, p01a); elem_math(x01.y, s01b, p01b);
        elem_math(x11.x, s11a, p11a); elem_math(x11.y, s11b, p11b);

        ssp0 += (p00a + p00b) + (p01a + p01b);
        ssp1 += (p10a + p10b) + (p11a + p11b);
        ssg0 += (s00a + s00b) + (s01a + s01b);
        ssg1 += (s10a + s10b) + (s11a + s11b);

        uint32_t apm[4] = { pack_bf16(x00.y, x00.x), pack_bf16(x10.y, x10.x),
                            pack_bf16(x01.y, x01.x), pack_bf16(x11.y, x11.x) };
        uint32_t asg[4] = { pack_bf16(s00b, s00a), pack_bf16(s10b, s10a),
                            pack_bf16(s01b, s01a), pack_bf16(s11b, s11a) };

        mma_bf16(cpm[0], apm, blo.x, blo.y);
        mma_bf16(csg[0], asg, blo.x, blo.y);
        mma_bf16(cpm[1], apm, blo.z, blo.w);
        mma_bf16(csg[1], asg, blo.z, blo.w);
        mma_bf16(cpm[2], apm, bhi.x, bhi.y);
        mma_bf16(csg[2], asg, bhi.x, bhi.y);
        mma_bf16(cpm[3], apm, bhi.z, bhi.w);
        mma_bf16(csg[3], asg, bhi.z, bhi.w);
    }

    int base_lo = (b * NROWP + r_lo) * NT;
    int base_hi = (b * NROWP + r_hi) * NT;
    #pragma unroll
    for (int nt = 0; nt < 4; ++nt) {
        int c = nt * 8 + kq;
        atomicAdd(&g_dotPM[base_lo + c],     cpm[nt][0]);
        atomicAdd(&g_dotPM[base_lo + c + 1], cpm[nt][1]);
        atomicAdd(&g_dotPM[base_hi + c],     cpm[nt][2]);
        atomicAdd(&g_dotPM[base_hi + c + 1], cpm[nt][3]);
        atomicAdd(&g_dotSIG[base_lo + c],     csg[nt][0]);
        atomicAdd(&g_dotSIG[base_lo + c + 1], csg[nt][1]);
        atomicAdd(&g_dotSIG[base_hi + c],     csg[nt][2]);
        atomicAdd(&g_dotSIG[base_hi + c + 1], csg[nt][3]);
    }
    atomicAdd(&g_sumSP[b * NROWP + r_lo],  ssp0);
    atomicAdd(&g_sumSP[b * NROWP + r_hi],  ssp1);
    atomicAdd(&g_sumSIG[b * NROWP + r_lo], ssg0);
    atomicAdd(&g_sumSIG[b * NROWP + r_hi], ssg1);
}

// ---------------- kernel 4: fused cost assembly + Hungarian (JV) ----------------
__global__ void k_hung(float* __restrict__ out) {
    const int b = blockIdx.x;
    const int lane = threadIdx.x;
    __shared__ float Cs[NT * NQ];
    __shared__ float u[NT + 1];
    __shared__ int   psh[NQ + 1];

    // assemble cost matrix [t][n] directly into shared
    for (int idx = lane; idx < NT * NQ; idx += 32) {
        int t = idx / NQ, n = idx - t * NQ;
        float spm  = g_sumSP[b * NROWP + n] * (1.0f / HW);
        float dpm  = g_dotPM[(b * NROWP + n) * NT + t] * (1.0f / HW);
        float dsg  = g_dotSIG[(b * NROWP + n) * NT + t];
        float den  = g_sumSIG[b * NROWP + n] + g_tsum[b * NT + t] + 1.0f;
        float dice = 1.0f - __fdividef(2.0f * dsg + 1.0f, den);
        Cs[idx] = g_classT[b * NT * NQ + idx] + (spm - dpm) + dice;
    }
    if (lane <= NT) u[lane] = 0.f;
    __syncwarp();

    float v0 = 0.f, v1 = 0.f, v2 = 0.f, v3 = 0.f;
    int   p0 = 0, p1 = 0, p2 = 0, p3 = 0;
    int   w0 = 0, w1 = 0, w2 = 0, w3 = 0;

    for (int i = 1; i <= NT; ++i) {
        float m0 = 1e30f, m1 = 1e30f, m2 = 1e30f, m3 = 1e30f;
        unsigned usedm = 0;
        if (lane == 0) p0 = i;
        int j0 = 0, i0 = i;   // i0 = p[j0]; known without a shuffle

        while (true) {
            if ((j0 & 31) == lane) usedm |= 1u << (j0 >> 5);
            float ui0 = u[i0];
            const float* Crow = Cs + (i0 - 1) * NQ;

            // payload: bj | (p[bj] << 8); lane owns p of its own slots
            uint32_t bk = 0xFFFFFFFFu; int bp = 127;
            if (lane >= 1 && !(usedm & 1u)) {
                float cur = Crow[lane - 1] - ui0 - v0;
                if (cur < m0) { m0 = cur; w0 = j0; }
                uint32_t k = fkey(m0);
                if (k < bk) { bk = k; bp = lane | (p0 << 8); }
            }
            if (!(usedm & 2u)) {
                float cur = Crow[31 + lane] - ui0 - v1;
                if (cur < m1) { m1 = cur; w1 = j0; }
                uint32_t k = fkey(m1);
                if (k < bk) { bk = k; bp = (32 + lane) | (p1 << 8); }
            }
            if (!(usedm & 4u)) {
                float cur = Crow[63 + lane] - ui0 - v2;
                if (cur < m2) { m2 = cur; w2 = j0; }
                uint32_t k = fkey(m2);
                if (k < bk) { bk = k; bp = (64 + lane) | (p2 << 8); }
            }
            if (lane <= 4 && !(usedm & 8u)) {
                float cur = Crow[95 + lane] - ui0 - v3;
                if (cur < m3) { m3 = cur; w3 = j0; }
                uint32_t k = fkey(m3);
                if (k < bk) { bk = k; bp = (96 + lane) | (p3 << 8); }
            }

            uint32_t kmin = __reduce_min_sync(0xffffffffu, bk);
            unsigned ball = __ballot_sync(0xffffffffu, bk == kmin);
            int src = __ffs(ball) - 1;
            int packed = __shfl_sync(0xffffffffu, bp, src);
            float delta = fkey_inv(kmin);

            if (usedm & 1u) { u[p0] += delta; v0 -= delta; } else m0 -= delta;
            if (usedm & 2u) { u[p1] += delta; v1 -= delta; } else m1 -= delta;
            if (usedm & 4u) { u[p2] += delta; v2 -= delta; } else m2 -= delta;
            if (usedm & 8u) { u[p3] += delta; v3 -= delta; } else m3 -= delta;
            __syncwarp();

            j0 = packed & 0xFF;
            int pj0 = packed >> 8;
            if (pj0 == 0) break;
            i0 = pj0;
        }

        // augment along 'way' chain
        while (j0 != 0) {
            int j1  = __shfl_sync(0xffffffffu, sel4i(w0, w1, w2, w3, j0 >> 5), j0 & 31);
            int pj1 = __shfl_sync(0xffffffffu, sel4i(p0, p1, p2, p3, j1 >> 5), j1 & 31);
            if ((j0 & 31) == lane) {
                int s = j0 >> 5;
                if (s == 0) p0 = pj1; else if (s == 1) p1 = pj1;
                else if (s == 2) p2 = pj1; else p3 = pj1;
            }
            j0 = j1;
        }
        __syncwarp();
    }

    psh[lane] = p0;
    psh[32 + lane] = p1;
    psh[64 + lane] = p2;
    if (lane <= 4) psh[96 + lane] = p3;
    __syncwarp();

    if (lane == 0) {
        int k = 0;
        for (int j = 1; j <= NQ; ++j) {
            if (psh[j]) {
                out[b * NT + k]           = (float)(j - 1);
                out[NB * NT + b * NT + k] = (float)(psh[j] - 1);
                ++k;
            }
        }
    }
}

// ---------------- launch ----------------
extern "C" void kernel_launch(void* const* d_in, const int* in_sizes, int n_in,
                              void* d_out, int out_size) {
    const float* logits = nullptr;
    const float* pmask  = nullptr;
    const float* tmask  = nullptr;
    const int*   labels = nullptr;

    for (int i = 0; i < n_in; ++i) {
        switch (in_sizes[i]) {
            case 64800:    logits = (const float*)d_in[i]; break;
            case 52428800: pmask  = (const float*)d_in[i]; break;
            case 256:      labels = (const int*)d_in[i];   break;
            default:
                if (in_sizes[i] == 67108864) tmask = (const float*)d_in[i];
                break;
        }
    }
    float* out = (float*)d_out;

    k_class<<<NB * NQ, 32>>>(logits, labels);
    k_tmask<<<dim3(HW / 512, NB), 256>>>(tmask);
    k_main<<<dim3(16, 7, NB), 256>>>(pmask);
    k_hung<<<NB, 32>>>(out);
}

// round 9
// speedup vs baseline: 1.1685x; 1.1685x over previous
#include <cuda_runtime.h>
#include <cstdint>

#define HW    65536
#define NQ    100
#define NT    32
#define NB    8
#define NROWP 112   // 7 mtiles * 16
#define NKT   4096  // k-tiles per batch (HW/16)

// ---------------- device scratch ----------------
__device__ uint4    g_bfrag[NB * NKT * 32 * 2];  // precomputed MMA B-fragments
__device__ float    g_tsum[NB * NT];
__device__ float    g_dotPM[NB * NROWP * NT];
__device__ float    g_dotSIG[NB * NROWP * NT];
__device__ float    g_sumSP[NB * NROWP];
__device__ float    g_sumSIG[NB * NROWP];
__device__ float    g_classT[NB * NT * NQ];      // [b][t][n]

// ---------------- helpers ----------------
__device__ __forceinline__ uint32_t pack_bf16(float hi, float lo) {
    uint32_t d;
    asm("cvt.rn.bf16x2.f32 %0, %1, %2;" : "=r"(d) : "f"(hi), "f"(lo));
    return d;
}

__device__ __forceinline__ void mma_bf16(float* c, const uint32_t* a,
                                         uint32_t b0, uint32_t b1) {
    asm volatile(
        "mma.sync.aligned.m16n8k16.row.col.f32.bf16.bf16.f32 "
        "{%0,%1,%2,%3}, {%4,%5,%6,%7}, {%8,%9}, {%0,%1,%2,%3};"
        : "+f"(c[0]), "+f"(c[1]), "+f"(c[2]), "+f"(c[3])
        : "r"(a[0]), "r"(a[1]), "r"(a[2]), "r"(a[3]), "r"(b0), "r"(b1));
}

__device__ __forceinline__ uint32_t fkey(float f) {
    uint32_t u = __float_as_uint(f);
    return (u & 0x80000000u) ? ~u : (u | 0x80000000u);
}
__device__ __forceinline__ float fkey_inv(uint32_t k) {
    uint32_t u = (k & 0x80000000u) ? (k ^ 0x80000000u) : ~k;
    return __uint_as_float(u);
}
__device__ __forceinline__ int sel4i(int a0, int a1, int a2, int a3, int s) {
    return s == 0 ? a0 : s == 1 ? a1 : s == 2 ? a2 : a3;
}

// ---------------- kernel 1: class cost (+ accumulator zeroing) ----------------
__global__ void k_class(const float* __restrict__ logits,
                        const int* __restrict__ labels) {
    int gid = blockIdx.x * 32 + threadIdx.x;
    for (int i = gid; i < NB * NROWP * NT; i += NB * NQ * 32) {
        g_dotPM[i] = 0.f; g_dotSIG[i] = 0.f;
    }
    if (gid < NB * NROWP) { g_sumSP[gid] = 0.f; g_sumSIG[gid] = 0.f; }
    if (gid < NB * NT)    { g_tsum[gid] = 0.f; }

    int b = blockIdx.x / NQ, n = blockIdx.x % NQ;
    int lane = threadIdx.x;
    __shared__ float sh[81];
    const float* L = logits + (size_t)(b * NQ + n) * 81;

    float x0 = L[lane];
    float x1 = (lane + 32 < 81) ? L[lane + 32] : -1e30f;
    float x2 = (lane + 64 < 81) ? L[lane + 64] : -1e30f;
    float m = fmaxf(x0, fmaxf(x1, x2));
    #pragma unroll
    for (int o = 16; o; o >>= 1) m = fmaxf(m, __shfl_xor_sync(0xffffffffu, m, o));

    float e0 = __expf(x0 - m);
    float e1 = (lane + 32 < 81) ? __expf(x1 - m) : 0.f;
    float e2 = (lane + 64 < 81) ? __expf(x2 - m) : 0.f;
    float s = e0 + e1 + e2;
    #pragma unroll
    for (int o = 16; o; o >>= 1) s += __shfl_xor_sync(0xffffffffu, s, o);

    sh[lane] = e0;
    if (lane + 32 < 81) sh[lane + 32] = e1;
    if (lane + 64 < 81) sh[lane + 64] = e2;
    __syncwarp();

    float inv = 1.0f / s;
    int lbl = labels[b * NT + lane];
    g_classT[(b * NT + lane) * NQ + n] = -sh[lbl] * inv;
}

// ---------------- kernel 2: target masks -> sums + B-fragments ----------------
__global__ __launch_bounds__(256) void k_tmask(const float* __restrict__ tgt) {
    __shared__ uint32_t sbits[512];
    const int b = blockIdx.y;
    const int tid = threadIdx.x;
    int p0 = blockIdx.x * 512 + tid * 2;
    int h = p0 >> 8, w = p0 & 255;
    size_t base = ((size_t)b * NT) * 262144 + (size_t)(2 * h) * 512 + 2 * w;
    uint32_t w0 = 0, w1 = 0;
    #pragma unroll
    for (int t = 0; t < 32; ++t) {
        float4 v = __ldcs((const float4*)(tgt + base + (size_t)t * 262144));
        w0 |= (uint32_t)(v.x != 0.0f) << t;
        w1 |= (uint32_t)(v.z != 0.0f) << t;
    }
    sbits[tid * 2]     = w0;
    sbits[tid * 2 + 1] = w1;

    int lane = tid & 31;
    int cnt = 0;
    #pragma unroll
    for (int t = 0; t < 32; ++t) {
        unsigned m0 = __ballot_sync(0xffffffffu, (w0 >> t) & 1u);
        unsigned m1 = __ballot_sync(0xffffffffu, (w1 >> t) & 1u);
        if (lane == t) cnt = __popc(m0) + __popc(m1);
    }
    atomicAdd(&g_tsum[b * NT + lane], (float)cnt);
    __syncthreads();

    const int warp = tid >> 5;
    const int kq = (lane & 3) << 1, rq = lane >> 2;
    #pragma unroll
    for (int i = 0; i < 4; ++i) {
        int ktl = warp * 4 + i;
        uint32_t t0 = sbits[ktl * 16 + kq]     >> rq;
        uint32_t t1 = sbits[ktl * 16 + kq + 1] >> rq;
        uint32_t t2 = sbits[ktl * 16 + kq + 8] >> rq;
        uint32_t t3 = sbits[ktl * 16 + kq + 9] >> rq;
        uint4 lo, hi;
        lo.x = ((t0 & 1u) * 0x3F80u)         | ((t1 & 1u) * 0x3F800000u);
        lo.y = ((t2 & 1u) * 0x3F80u)         | ((t3 & 1u) * 0x3F800000u);
        lo.z = (((t0 >> 8) & 1u) * 0x3F80u)  | (((t1 >> 8) & 1u) * 0x3F800000u);
        lo.w = (((t2 >> 8) & 1u) * 0x3F80u)  | (((t3 >> 8) & 1u) * 0x3F800000u);
        hi.x = (((t0 >> 16) & 1u) * 0x3F80u) | (((t1 >> 16) & 1u) * 0x3F800000u);
        hi.y = (((t2 >> 16) & 1u) * 0x3F80u) | (((t3 >> 16) & 1u) * 0x3F800000u);
        hi.z = (((t0 >> 24) & 1u) * 0x3F80u) | (((t1 >> 24) & 1u) * 0x3F800000u);
        hi.w = (((t2 >> 24) & 1u) * 0x3F80u) | (((t3 >> 24) & 1u) * 0x3F800000u);
        int kt = blockIdx.x * 32 + ktl;
        uint4* dst = g_bfrag + ((size_t)(b * NKT + kt) * 32 + lane) * 2;
        dst[0] = lo;
        dst[1] = hi;
    }
}

// ---------------- kernel 3: fully bf16x2 elementwise + MMA ----------------
__global__ __launch_bounds__(256) void k_main(const float* __restrict__ pm) {
    const int b = blockIdx.z, mt = blockIdx.y;
    const int warp = threadIdx.x >> 5, lane = threadIdx.x & 31;
    const int kstart = blockIdx.x * (HW / 16) + warp * (HW / 16 / 8);
    const int rq = lane >> 2;
    const int kq = (lane & 3) << 1;
    const int r_lo = mt * 16 + rq, r_hi = r_lo + 8;
    const int rl = min(r_lo, NQ - 1), rh = min(r_hi, NQ - 1);

    const float* pmb = pm + (size_t)b * NQ * HW;
    const uint4* bf  = g_bfrag + ((size_t)(b * NKT + (kstart >> 4)) * 32 + lane) * 2;

    const uint32_t HALF2  = 0x3F003F00u;  // bf16x2 (0.5, 0.5)
    const uint32_t NHALF2 = 0xBF00BF00u;  // bf16x2 (-0.5, -0.5)
    const uint32_t ONES2  = 0x3F803F80u;  // bf16x2 (1.0, 1.0)

    float cpm[4][4], csg[4][4], csum[4];
    #pragma unroll
    for (int i = 0; i < 4; ++i) {
        csum[i] = 0.f;
        #pragma unroll
        for (int j = 0; j < 4; ++j) { cpm[i][j] = 0.f; csg[i][j] = 0.f; }
    }
    float splog0 = 0.f, splog1 = 0.f;

    #pragma unroll 2
    for (int it = 0; it < 32; ++it) {
        int k0 = kstart + it * 16 + kq;
        float2 x00 = __ldcs((const float2*)(pmb + (size_t)rl * HW + k0));
        float2 x10 = __ldcs((const float2*)(pmb + (size_t)rh * HW + k0));
        float2 x01 = __ldcs((const float2*)(pmb + (size_t)rl * HW + k0 + 8));
        float2 x11 = __ldcs((const float2*)(pmb + (size_t)rh * HW + k0 + 8));
        uint4 blo = bf[it * 64];
        uint4 bhi = bf[it * 64 + 1];

        uint32_t apm[4] = { pack_bf16(x00.y, x00.x), pack_bf16(x10.y, x10.x),
                            pack_bf16(x01.y, x01.x), pack_bf16(x11.y, x11.x) };

        uint32_t asg[4], aq[4];
        #pragma unroll
        for (int q = 0; q < 4; ++q) {
            uint32_t th;
            asm("mul.rn.bf16x2 %0, %1, %2;" : "=r"(th) : "r"(apm[q]), "r"(HALF2));
            asm("tanh.approx.bf16x2 %0, %1;" : "=r"(th) : "r"(th));
            asm("fma.rn.bf16x2 %0, %1, %2, %3;" : "=r"(asg[q]) : "r"(th), "r"(HALF2),  "r"(HALF2));
            asm("fma.rn.bf16x2 %0, %1, %2, %3;" : "=r"(aq[q])  : "r"(th), "r"(NHALF2), "r"(HALF2));
        }

        // softplus row sums: product of the 4 sigmoid(-x) per row, one log
        uint32_t prL, prH;
        asm("mul.rn.bf16x2 %0, %1, %2;" : "=r"(prL) : "r"(aq[0]), "r"(aq[2]));
        asm("mul.rn.bf16x2 %0, %1, %2;" : "=r"(prH) : "r"(aq[1]), "r"(aq[3]));
        float fL = __uint_as_float(prL << 16) * __uint_as_float(prL & 0xFFFF0000u);
        float fH = __uint_as_float(prH << 16) * __uint_as_float(prH & 0xFFFF0000u);
        splog0 += __logf(fL);
        splog1 += __logf(fH);

        mma_bf16(cpm[0], apm, blo.x, blo.y);
        mma_bf16(csg[0], asg, blo.x, blo.y);
        mma_bf16(cpm[1], apm, blo.z, blo.w);
        mma_bf16(csg[1], asg, blo.z, blo.w);
        mma_bf16(cpm[2], apm, bhi.x, bhi.y);
        mma_bf16(csg[2], asg, bhi.x, bhi.y);
        mma_bf16(cpm[3], apm, bhi.z, bhi.w);
        mma_bf16(csg[3], asg, bhi.z, bhi.w);
        mma_bf16(csum,   asg, ONES2, ONES2);   // row sums of sigmoid (all cols equal)
    }

    int base_lo = (b * NROWP + r_lo) * NT;
    int base_hi = (b * NROWP + r_hi) * NT;
    #pragma unroll
    for (int nt = 0; nt < 4; ++nt) {
        int c = nt * 8 + kq;
        atomicAdd(&g_dotPM[base_lo + c],     cpm[nt][0]);
        atomicAdd(&g_dotPM[base_lo + c + 1], cpm[nt][1]);
        atomicAdd(&g_dotPM[base_hi + c],     cpm[nt][2]);
        atomicAdd(&g_dotPM[base_hi + c + 1], cpm[nt][3]);
        atomicAdd(&g_dotSIG[base_lo + c],     csg[nt][0]);
        atomicAdd(&g_dotSIG[base_lo + c + 1], csg[nt][1]);
        atomicAdd(&g_dotSIG[base_hi + c],     csg[nt][2]);
        atomicAdd(&g_dotSIG[base_hi + c + 1], csg[nt][3]);
    }
    atomicAdd(&g_sumSP[b * NROWP + r_lo],  -splog0);   // per-lane partial: all lanes add
    atomicAdd(&g_sumSP[b * NROWP + r_hi],  -splog1);
    if (kq == 0) {
        // csum columns are identical (B=ones): FULL tile row-sum per lane.
        // Only one lane per quad may contribute (fixes R8's 4x overcount).
        atomicAdd(&g_sumSIG[b * NROWP + r_lo], csum[0]);
        atomicAdd(&g_sumSIG[b * NROWP + r_hi], csum[2]);
    }
}

// ---------------- kernel 4: cost assembly + JV with greedy init ----------------
__global__ void k_hung(float* __restrict__ out) {
    const int b = blockIdx.x;
    const int lane = threadIdx.x;
    __shared__ float Cs[NT * NQ];
    __shared__ float u[NT + 1];
    __shared__ int   psh[NQ + 1];

    for (int idx = lane; idx < NT * NQ; idx += 32) {
        int t = idx / NQ, n = idx - t * NQ;
        float spm  = g_sumSP[b * NROWP + n] * (1.0f / HW);
        float dpm  = g_dotPM[(b * NROWP + n) * NT + t] * (1.0f / HW);
        float dsg  = g_dotSIG[(b * NROWP + n) * NT + t];
        float den  = g_sumSIG[b * NROWP + n] + g_tsum[b * NT + t] + 1.0f;
        float dice = 1.0f - __fdividef(2.0f * dsg + 1.0f, den);
        Cs[idx] = g_classT[b * NT * NQ + idx] + (spm - dpm) + dice;
    }
    __syncwarp();

    float v0 = 0.f, v1 = 0.f, v2 = 0.f, v3 = 0.f;
    int   p0 = 0, p1 = 0, p2 = 0, p3 = 0;
    int   w0 = 0, w1 = 0, w2 = 0, w3 = 0;

    // ---- greedy init: row reduction + tight-arc matching ----
    uint32_t cm0 = 1u, cm1 = 0, cm2 = 0, cm3 = 0;
    uint32_t freerows = 0;
    for (int i = 1; i <= NT; ++i) {
        const float* Crow = Cs + (i - 1) * NQ;
        uint32_t bk = 0xFFFFFFFFu;
        if (lane >= 1) { uint32_t k = (fkey(Crow[lane - 1]) & ~127u) | lane;         if (k < bk) bk = k; }
        {               uint32_t k = (fkey(Crow[31 + lane]) & ~127u) | (32 + lane);  if (k < bk) bk = k; }
        {               uint32_t k = (fkey(Crow[63 + lane]) & ~127u) | (64 + lane);  if (k < bk) bk = k; }
        if (lane <= 4) { uint32_t k = (fkey(Crow[95 + lane]) & ~127u) | (96 + lane); if (k < bk) bk = k; }
        uint32_t kmin = __reduce_min_sync(0xffffffffu, bk);
        int js = kmin & 127;
        u[i] = fkey_inv(kmin & ~127u);     // floor => dual-feasible
        int slot = js >> 5;
        uint32_t bit = 1u << (js & 31);
        bool taken = (slot == 0 ? cm0 : slot == 1 ? cm1 : slot == 2 ? cm2 : cm3) & bit;
        if (!taken) {
            if ((js & 31) == lane) {
                if (slot == 0) p0 = i; else if (slot == 1) p1 = i;
                else if (slot == 2) p2 = i; else p3 = i;
            }
            if (slot == 0) cm0 |= bit; else if (slot == 1) cm1 |= bit;
            else if (slot == 2) cm2 |= bit; else cm3 |= bit;
        } else {
            freerows |= 1u << (i - 1);
        }
    }
    __syncwarp();

    // ---- Dijkstra phases for unmatched rows ----
    while (freerows) {
        int i = __ffs(freerows);
        freerows &= freerows - 1;
        float m0 = 1e30f, m1 = 1e30f, m2 = 1e30f, m3 = 1e30f;
        unsigned usedm = 0;
        if (lane == 0) p0 = i;
        int j0 = 0, i0 = i;

        while (true) {
            if ((j0 & 31) == lane) usedm |= 1u << (j0 >> 5);
            float ui0 = u[i0];
            const float* Crow = Cs + (i0 - 1) * NQ;

            uint32_t bk = 0xFFFFFFFFu; int bp = 127;
            if (lane >= 1 && !(usedm & 1u)) {
                float cur = Crow[lane - 1] - ui0 - v0;
                if (cur < m0) { m0 = cur; w0 = j0; }
                uint32_t k = fkey(m0);
                if (k < bk) { bk = k; bp = lane | (p0 << 8); }
            }
            if (!(usedm & 2u)) {
                float cur = Crow[31 + lane] - ui0 - v1;
                if (cur < m1) { m1 = cur; w1 = j0; }
                uint32_t k = fkey(m1);
                if (k < bk) { bk = k; bp = (32 + lane) | (p1 << 8); }
            }
            if (!(usedm & 4u)) {
                float cur = Crow[63 + lane] - ui0 - v2;
                if (cur < m2) { m2 = cur; w2 = j0; }
                uint32_t k = fkey(m2);
                if (k < bk) { bk = k; bp = (64 + lane) | (p2 << 8); }
            }
            if (lane <= 4 && !(usedm & 8u)) {
                float cur = Crow[95 + lane] - ui0 - v3;
                if (cur < m3) { m3 = cur; w3 = j0; }
                uint32_t k = fkey(m3);
                if (k < bk) { bk = k; bp = (96 + lane) | (p3 << 8); }
            }

            uint32_t kmin = __reduce_min_sync(0xffffffffu, bk);
            unsigned ball = __ballot_sync(0xffffffffu, bk == kmin);
            int src = __ffs(ball) - 1;
            int packed = __shfl_sync(0xffffffffu, bp, src);
            float delta = fkey_inv(kmin);

            if (usedm & 1u) { u[p0] += delta; v0 -= delta; } else m0 -= delta;
            if (usedm & 2u) { u[p1] += delta; v1 -= delta; } else m1 -= delta;
            if (usedm & 4u) { u[p2] += delta; v2 -= delta; } else m2 -= delta;
            if (usedm & 8u) { u[p3] += delta; v3 -= delta; } else m3 -= delta;
            __syncwarp();

            j0 = packed & 0xFF;
            int pj0 = packed >> 8;
            if (pj0 == 0) break;
            i0 = pj0;
        }

        while (j0 != 0) {
            int j1  = __shfl_sync(0xffffffffu, sel4i(w0, w1, w2, w3, j0 >> 5), j0 & 31);
            int pj1 = __shfl_sync(0xffffffffu, sel4i(p0, p1, p2, p3, j1 >> 5), j1 & 31);
            if ((j0 & 31) == lane) {
                int s = j0 >> 5;
                if (s == 0) p0 = pj1; else if (s == 1) p1 = pj1;
                else if (s == 2) p2 = pj1; else p3 = pj1;
            }
            j0 = j1;
        }
        __syncwarp();
    }

    psh[lane] = p0;
    psh[32 + lane] = p1;
    psh[64 + lane] = p2;
    if (lane <= 4) psh[96 + lane] = p3;
    __syncwarp();

    if (lane == 0) {
        int k = 0;
        for (int j = 1; j <= NQ; ++j) {
            if (psh[j]) {
                out[b * NT + k]           = (float)(j - 1);
                out[NB * NT + b * NT + k] = (float)(psh[j] - 1);
                ++k;
            }
        }
    }
}

// ---------------- launch ----------------
extern "C" void kernel_launch(void* const* d_in, const int* in_sizes, int n_in,
                              void* d_out, int out_size) {
    const float* logits = nullptr;
    const float* pmask  = nullptr;
    const float* tmask  = nullptr;
    const int*   labels = nullptr;

    for (int i = 0; i < n_in; ++i) {
        switch (in_sizes[i]) {
            case 64800:    logits = (const float*)d_in[i]; break;
            case 52428800: pmask  = (const float*)d_in[i]; break;
            case 256:      labels = (const int*)d_in[i];   break;
            default:
                if (in_sizes[i] == 67108864) tmask = (const float*)d_in[i];
                break;
        }
    }
    float* out = (float*)d_out;

    k_class<<<NB * NQ, 32>>>(logits, labels);
    k_tmask<<<dim3(HW / 512, NB), 256>>>(tmask);
    k_main<<<dim3(16, 7, NB), 256>>>(pmask);
    k_hung<<<NB, 32>>>(out);
}